// round 12
// baseline (speedup 1.0000x reference)
#include <cuda_runtime.h>
#include <math.h>
#include <stdint.h>

#define BB    64
#define TT    1024
#define HH    512
#define INSZ  8
#define KZZ   3
#define NGATE 18
#define NBLK  148
#define NTHR  256
// smem: phase A = U tile [128][64] + h tile [64][132] floats; phase C = l [512][8] floats
#define SMEM_BYTES ((128*64 + 64*132) * 4)

// ---------------- persistent device state (no allocations allowed) ----------------
__device__ float g_h[BB*HH];
__device__ float g_c[BB*HH];
__device__ float g_act[(size_t)NGATE*BB*HH];
__device__ volatile int g_bar_count;
__device__ volatile int g_bar_gen;

// ---------------- grid-wide barrier (all CTAs resident: 148 CTAs, 1/SM min) -------
__device__ __forceinline__ void grid_barrier() {
    __syncthreads();
    if (threadIdx.x == 0) {
        int gen = g_bar_gen;
        __threadfence();
        int ticket = atomicAdd((int*)&g_bar_count, 1);
        if (ticket == (int)gridDim.x - 1) {
            g_bar_count = 0;
            __threadfence();
            g_bar_gen = gen + 1;
        } else {
            while (g_bar_gen == gen) { __nanosleep(64); }
        }
        __threadfence();
    }
    __syncthreads();
}

__device__ __forceinline__ float sigmoidf_(float x) { return 1.0f / (1.0f + expf(-x)); }

// ---------------- init: zero h0/c0 and reset barrier state (runs every launch) ----
__global__ void __launch_bounds__(NTHR) init_kernel() {
    int i = blockIdx.x * blockDim.x + threadIdx.x;
    if (i == 0) { g_bar_count = 0; g_bar_gen = 0; }
    int n = gridDim.x * blockDim.x;
    for (int e = i; e < BB*HH; e += n) { g_h[e] = 0.0f; g_c[e] = 0.0f; }
}

// ---------------- persistent recurrent kernel -------------------------------------
__global__ void __launch_bounds__(NTHR, 1) lstm_kernel(
    const float* __restrict__ Y,
    const float* __restrict__ x1, const float* __restrict__ x2,
    const float* __restrict__ x3, const float* __restrict__ x4,
    const float* __restrict__ x5, const float* __restrict__ x6,
    const float* __restrict__ x7,
    const float* __restrict__ W_i, const float* __restrict__ U_i, const float* __restrict__ b_i,
    const float* __restrict__ W_f, const float* __restrict__ U_f, const float* __restrict__ b_f,
    const float* __restrict__ W_c, const float* __restrict__ U_c, const float* __restrict__ b_c,
    const float* __restrict__ W_o, const float* __restrict__ U_o, const float* __restrict__ b_o,
    const float* __restrict__ W_i_x, const float* __restrict__ U_i_x, const float* __restrict__ b_i_x,
    const float* __restrict__ W_c_x, const float* __restrict__ U_c_x, const float* __restrict__ b_c_x,
    const float* __restrict__ W_a, const float* __restrict__ b_a,
    float* __restrict__ out_hT, float* __restrict__ out_seq)
{
    extern __shared__ float smem[];
    const int ct  = blockIdx.x;
    const int tid = threadIdx.x;

    // ---- phase A thread mapping: 16 g-groups (4 cols) x 16 b-groups (4 rows) ----
    const int gq = tid & 15;
    const int bq = tid >> 4;

    // ---- phase A per-CTA uniform setup: gate = ct/8, columns [(ct%8)*64, +64) ---
    const float* Ubase = 0; const float* Wbase = 0; const float* bias = 0;
    const float* xin = 0;
    int gate = 0, gbase0 = 0, nin = 0, isTanh = 0;
    if (ct < 144) {
        gate   = ct >> 3;
        gbase0 = (ct & 7) * 64;
        if (gate < 4) {
            const float* Us[4] = {U_i, U_f, U_c, U_o};
            const float* Ws[4] = {W_i, W_f, W_c, W_o};
            const float* bs[4] = {b_i, b_f, b_c, b_o};
            Ubase = Us[gate]; Wbase = Ws[gate]; bias = bs[gate];
            xin = Y; nin = INSZ; isTanh = (gate == 2);
        } else if (gate < 11) {
            int j = gate - 4;                       // i_x channel
            Ubase = U_i_x + (size_t)j * HH * HH;
            Wbase = W_i_x + (size_t)j * KZZ * HH;
            bias  = b_i_x + (size_t)j * HH;
            xin   = (j == 0) ? x1 : x2;             // xi = [x1, x2, x2, x2, x2, x2, x2]
            nin = KZZ; isTanh = 0;
        } else {
            int j = gate - 11;                      // c_x channel
            Ubase = U_c_x + (size_t)j * HH * HH;
            Wbase = W_c_x + (size_t)j * KZZ * HH;
            bias  = b_c_x + (size_t)j * HH;
            const float* xs[7] = {x1, x2, x3, x4, x5, x6, x7};
            xin = xs[j];                            // xc = [x1..x7]
            nin = KZZ; isTanh = 1;
        }
    }

    float* sh_u = smem;             // [128][64]
    float* sh_h = smem + 128*64;    // [64][132] (padded: avoids 2-way bank conflict)

    for (int t = 0; t < TT; t++) {
        // ======================= Phase A: GEMM1 + gate activations ===============
        if (ct < 144) {
            float4 a0 = {0,0,0,0}, a1 = {0,0,0,0}, a2 = {0,0,0,0}, a3 = {0,0,0,0};
            for (int kc = 0; kc < 4; kc++) {
                // cooperative load: U tile [128 k][64 g]
                for (int i = tid; i < 2048; i += NTHR) {
                    int r = i >> 4, c4 = (i & 15) << 2;
                    *(float4*)(sh_u + r*64 + c4) =
                        *(const float4*)(Ubase + (size_t)(kc*128 + r)*HH + gbase0 + c4);
                }
                // cooperative load: h tile [64 b][128 k], row stride 132
                for (int i = tid; i < 2048; i += NTHR) {
                    int b = i >> 5, c4 = (i & 31) << 2;
                    *(float4*)(sh_h + b*132 + c4) =
                        *(const float4*)(g_h + b*HH + kc*128 + c4);
                }
                __syncthreads();
                const float* up = sh_u + (gq << 2);
                const float* hp = sh_h + bq*4*132;
                #pragma unroll 4
                for (int k = 0; k < 128; k++) {
                    float4 u4 = *(const float4*)(up + (k << 6));
                    float h0 = hp[k], h1 = hp[132 + k], h2 = hp[264 + k], h3 = hp[396 + k];
                    a0.x += h0*u4.x; a0.y += h0*u4.y; a0.z += h0*u4.z; a0.w += h0*u4.w;
                    a1.x += h1*u4.x; a1.y += h1*u4.y; a1.z += h1*u4.z; a1.w += h1*u4.w;
                    a2.x += h2*u4.x; a2.y += h2*u4.y; a2.z += h2*u4.z; a2.w += h2*u4.w;
                    a3.x += h3*u4.x; a3.y += h3*u4.y; a3.z += h3*u4.z; a3.w += h3*u4.w;
                }
                __syncthreads();
            }
            float accv[4][4] = {
                {a0.x, a0.y, a0.z, a0.w},
                {a1.x, a1.y, a1.z, a1.w},
                {a2.x, a2.y, a2.z, a2.w},
                {a3.x, a3.y, a3.z, a3.w}};
            #pragma unroll
            for (int bi = 0; bi < 4; bi++) {
                int b = bq*4 + bi;
                float xv[INSZ];
                #pragma unroll
                for (int c = 0; c < INSZ; c++)
                    if (c < nin) xv[c] = xin[((size_t)b*nin + c)*TT + t];
                #pragma unroll
                for (int gi = 0; gi < 4; gi++) {
                    int g = gbase0 + (gq << 2) + gi;
                    float s = bias[g] + accv[bi][gi];
                    for (int c = 0; c < nin; c++) s += xv[c] * Wbase[c*HH + g];
                    float a = isTanh ? tanhf(s) : sigmoidf_(s);
                    g_act[((size_t)gate*BB + b)*HH + g] = a;
                }
            }
        }
        grid_barrier();   // g_act complete

        // ======================= Phase C: l, GEMM2, softmax, state update ========
        if (ct < 128) {
            int b  = ct >> 1;
            int gb = (ct & 1) << 8;            // 0 or 256
            float* sh_l = smem;                // [512 h][8 k]
            #pragma unroll
            for (int k = 0; k < 8; k++) {
                int gA = (k == 0) ? 2 : (10 + k);   // candidate gate (tanh)
                int gB = (k == 0) ? 0 : (3 + k);    // input gate (sigmoid)
                const float* pa = g_act + ((size_t)gA*BB + b)*HH;
                const float* pb = g_act + ((size_t)gB*BB + b)*HH;
                for (int hh = tid; hh < HH; hh += NTHR)
                    sh_l[hh*8 + k] = pa[hh] * pb[hh];
            }
            __syncthreads();

            int g = gb + tid;                  // 256 threads -> 256 columns
            float acc[8];
            #pragma unroll
            for (int k = 0; k < 8; k++) acc[k] = 0.0f;
            const float* wp = W_a + g;
            #pragma unroll 4
            for (int hh = 0; hh < HH; hh++) {
                float w = wp[(size_t)hh*HH];
                float4 p0 = *(const float4*)(sh_l + hh*8);
                float4 p1 = *(const float4*)(sh_l + hh*8 + 4);
                acc[0] += p0.x*w; acc[1] += p0.y*w; acc[2] += p0.z*w; acc[3] += p0.w*w;
                acc[4] += p1.x*w; acc[5] += p1.y*w; acc[6] += p1.z*w; acc[7] += p1.w*w;
            }
            float cv = g_c[b*HH + g];
            float ba = b_a[g];
            float u[8], m = -1e30f;
            #pragma unroll
            for (int k = 0; k < 8; k++) { u[k] = tanhf(acc[k]*cv + ba); m = fmaxf(m, u[k]); }
            float e[8], es = 0.0f;
            #pragma unroll
            for (int k = 0; k < 8; k++) { e[k] = expf(u[k] - m); es += e[k]; }
            float inv = 1.0f / es;
            float L = 0.0f;
            #pragma unroll
            for (int k = 0; k < 8; k++) L += e[k] * inv * sh_l[g*8 + k];
            float f  = g_act[((size_t)1*BB + b)*HH + g];
            float o  = g_act[((size_t)3*BB + b)*HH + g];
            float cn = f*cv + L;
            float hn = o * tanhf(cn);
            g_c[b*HH + g] = cn;
            g_h[b*HH + g] = hn;
            out_seq[((size_t)b*TT + t)*HH + g] = hn;     // hidden_seq [B,T,H]
            if (t == TT - 1 && out_hT) out_hT[b*HH + g] = hn;
        }
        grid_barrier();   // h/c updated for next step
    }
}

// ---------------- launch ----------------------------------------------------------
extern "C" void kernel_launch(void* const* d_in, const int* in_sizes, int n_in,
                              void* d_out, int out_size) {
    (void)in_sizes; (void)n_in;
    const float* Y    = (const float*)d_in[0];
    const float* x1   = (const float*)d_in[1];
    const float* x2   = (const float*)d_in[2];
    const float* x3   = (const float*)d_in[3];
    const float* x4   = (const float*)d_in[4];
    const float* x5   = (const float*)d_in[5];
    const float* x6   = (const float*)d_in[6];
    const float* x7   = (const float*)d_in[7];
    const float* W_i  = (const float*)d_in[8];
    const float* U_i  = (const float*)d_in[9];
    const float* b_i  = (const float*)d_in[10];
    const float* W_f  = (const float*)d_in[11];
    const float* U_f  = (const float*)d_in[12];
    const float* b_f  = (const float*)d_in[13];
    const float* W_c  = (const float*)d_in[14];
    const float* U_c  = (const float*)d_in[15];
    const float* b_c  = (const float*)d_in[16];
    const float* W_o  = (const float*)d_in[17];
    const float* U_o  = (const float*)d_in[18];
    const float* b_o  = (const float*)d_in[19];
    const float* W_i_x = (const float*)d_in[20];
    const float* U_i_x = (const float*)d_in[21];
    const float* b_i_x = (const float*)d_in[22];
    const float* W_c_x = (const float*)d_in[23];
    const float* U_c_x = (const float*)d_in[24];
    const float* b_c_x = (const float*)d_in[25];
    const float* W_a  = (const float*)d_in[26];
    const float* b_a  = (const float*)d_in[27];

    float* out = (float*)d_out;
    float* out_hT; float* out_seq;
    if (out_size >= BB*HH + BB*TT*HH) { out_hT = out; out_seq = out + BB*HH; }
    else                              { out_hT = 0;   out_seq = out; }

    cudaFuncSetAttribute(lstm_kernel, cudaFuncAttributeMaxDynamicSharedMemorySize, SMEM_BYTES);

    init_kernel<<<32, NTHR>>>();
    lstm_kernel<<<NBLK, NTHR, SMEM_BYTES>>>(
        Y, x1, x2, x3, x4, x5, x6, x7,
        W_i, U_i, b_i, W_f, U_f, b_f, W_c, U_c, b_c, W_o, U_o, b_o,
        W_i_x, U_i_x, b_i_x, W_c_x, U_c_x, b_c_x, W_a, b_a,
        out_hT, out_seq);
}

// round 14
// speedup vs baseline: 1.5070x; 1.5070x over previous
#include <cuda_runtime.h>
#include <math.h>
#include <stdint.h>

#define BB    64
#define TT    1024
#define HH    512
#define INSZ  8
#define KZZ   3
#define NBLK  148
#define NTHR  256
#define HSTR  132                    // padded h-tile row stride (floats)
#define HBUF  (64*HSTR)              // 8448 floats per h buffer
#define U_FLOATS (512*64)            // 32768 floats (128KB) resident U tile
#define SMEM_FLOATS (U_FLOATS + 2*HBUF)
#define SMEM_BYTES  (SMEM_FLOATS*4)  // 198656 B

// ---------------- persistent device state ----------------
__device__ float g_h[BB*HH];
__device__ float g_c[BB*HH];
__device__ float g_act[(size_t)18*BB*HH];
__device__ volatile int g_bar_count;
__device__ volatile int g_bar_gen;

// ---------------- grid barrier (148 CTAs, 1/SM, all resident) --------------
__device__ __forceinline__ void grid_barrier() {
    __threadfence();                       // publish this thread's writes (L2)
    __syncthreads();
    if (threadIdx.x == 0) {
        int gen = g_bar_gen;
        int ticket = atomicAdd((int*)&g_bar_count, 1);
        if (ticket == NBLK - 1) {
            g_bar_count = 0;
            __threadfence();
            g_bar_gen = gen + 1;
        } else {
            while (g_bar_gen == gen) { __nanosleep(32); }
        }
    }
    __syncthreads();
}

__device__ __forceinline__ float fast_sigmoid(float x) {
    return __fdividef(1.0f, 1.0f + __expf(-x));
}
__device__ __forceinline__ float fast_tanh(float x) {
    // 1 - 2/(e^{2x}+1): monotone-safe at +/-inf (no NaN)
    return 1.0f - __fdividef(2.0f, __expf(2.0f * x) + 1.0f);
}

#define FMA4(acc, s, u) { acc.x += (s)*(u).x; acc.y += (s)*(u).y; acc.z += (s)*(u).z; acc.w += (s)*(u).w; }

// ---------------- init ------------------------------------------------------
__global__ void __launch_bounds__(NTHR) init_kernel() {
    int i = blockIdx.x * blockDim.x + threadIdx.x;
    if (i == 0) { g_bar_count = 0; g_bar_gen = 0; }
    int n = gridDim.x * blockDim.x;
    for (int e = i; e < BB*HH; e += n) { g_h[e] = 0.0f; g_c[e] = 0.0f; }
}

// ---------------- persistent recurrent kernel -------------------------------
__global__ void __launch_bounds__(NTHR, 1) lstm_kernel(
    const float* __restrict__ Y,
    const float* __restrict__ x1, const float* __restrict__ x2,
    const float* __restrict__ x3, const float* __restrict__ x4,
    const float* __restrict__ x5, const float* __restrict__ x6,
    const float* __restrict__ x7,
    const float* __restrict__ W_i, const float* __restrict__ U_i, const float* __restrict__ b_i,
    const float* __restrict__ W_f, const float* __restrict__ U_f, const float* __restrict__ b_f,
    const float* __restrict__ W_c, const float* __restrict__ U_c, const float* __restrict__ b_c,
    const float* __restrict__ W_o, const float* __restrict__ U_o, const float* __restrict__ b_o,
    const float* __restrict__ W_i_x, const float* __restrict__ U_i_x, const float* __restrict__ b_i_x,
    const float* __restrict__ W_c_x, const float* __restrict__ U_c_x, const float* __restrict__ b_c_x,
    const float* __restrict__ W_a, const float* __restrict__ b_a,
    float* __restrict__ out_hT, float* __restrict__ out_seq)
{
    extern __shared__ float smem[];
    const int ct  = blockIdx.x;
    const int tid = threadIdx.x;
    const int gq  = tid & 15;       // 16 g-groups of 4 cols
    const int bq  = tid >> 4;       // 16 b-groups of 4 rows

    float* sh_u = smem;                 // [512 k][64 g], resident all steps
    float* sh_h = smem + U_FLOATS;      // 2 x [64 b][132 stride] double buffer
    float* sh_l = smem + U_FLOATS;      // phase C alias: [512 h][8 k]

    // ---- phase A per-CTA setup: gate = ct/8, cols [(ct%8)*64, +64) ----------
    const float* Ubase = 0; const float* Wbase = 0; const float* bias = 0;
    const float* xin = 0;
    int gate = 0, gbase0 = 0, nin = 0, isTanh = 0;
    if (ct < 144) {
        gate   = ct >> 3;
        gbase0 = (ct & 7) * 64;
        if (gate < 4) {
            const float* Us[4] = {U_i, U_f, U_c, U_o};
            const float* Ws[4] = {W_i, W_f, W_c, W_o};
            const float* bs[4] = {b_i, b_f, b_c, b_o};
            Ubase = Us[gate]; Wbase = Ws[gate]; bias = bs[gate];
            xin = Y; nin = INSZ; isTanh = (gate == 2);
        } else if (gate < 11) {
            int j = gate - 4;                       // i_x channel
            Ubase = U_i_x + (size_t)j * HH * HH;
            Wbase = W_i_x + (size_t)j * KZZ * HH;
            bias  = b_i_x + (size_t)j * HH;
            xin   = (j == 0) ? x1 : x2;             // xi = [x1,x2,x2,x2,x2,x2,x2]
            nin = KZZ; isTanh = 0;
        } else {
            int j = gate - 11;                      // c_x channel
            Ubase = U_c_x + (size_t)j * HH * HH;
            Wbase = W_c_x + (size_t)j * KZZ * HH;
            bias  = b_c_x + (size_t)j * HH;
            const float* xs[7] = {x1, x2, x3, x4, x5, x6, x7};
            xin = xs[j];                            // xc = [x1..x7]
            nin = KZZ; isTanh = 1;
        }
    }

    // ---- one-time: resident U tile + hoisted input-proj weights/bias --------
    float wv[32];            // [gi][c], zero-padded to c=8
    float biasv[4];
    if (ct < 144) {
        for (int i = tid; i < 8192; i += NTHR) {     // 8192 float4 = 32768 floats
            int k = i >> 4, c4 = (i & 15) << 2;
            *(float4*)(sh_u + k*64 + c4) =
                *(const float4*)(Ubase + (size_t)k*HH + gbase0 + c4);
        }
        #pragma unroll
        for (int gi = 0; gi < 4; gi++) {
            int g = gbase0 + (gq << 2) + gi;
            biasv[gi] = bias[g];
            #pragma unroll
            for (int c = 0; c < 8; c++)
                wv[gi*8 + c] = (c < nin) ? Wbase[c*HH + g] : 0.0f;
        }
    }
    __syncthreads();

    for (int t = 0; t < TT; t++) {
        // ======================= Phase A: GEMM1 + activations ================
        if (ct < 144) {
            // prologue: load h chunk 0 into buffer 0
            for (int i = tid; i < 2048; i += NTHR) {
                int b = i >> 5, c4 = (i & 31) << 2;
                *(float4*)(sh_h + b*HSTR + c4) =
                    __ldcg((const float4*)(g_h + b*HH + c4));
            }
            __syncthreads();

            float4 a0 = {0,0,0,0}, a1 = a0, a2 = a0, a3 = a0;
            float4 pre[8];
            for (int kc = 0; kc < 4; kc++) {
                float* cur = sh_h + (kc & 1) * HBUF;
                if (kc < 3) {               // prefetch next chunk into regs
                    #pragma unroll
                    for (int j = 0; j < 8; j++) {
                        int i = tid + j*NTHR;
                        int b = i >> 5, c4 = (i & 31) << 2;
                        pre[j] = __ldcg((const float4*)(g_h + b*HH + (kc+1)*128 + c4));
                    }
                }
                const float* up = sh_u + (kc*128)*64 + (gq << 2);
                const float* hp = cur + (bq << 2)*HSTR;
                #pragma unroll 2
                for (int kk = 0; kk < 128; kk += 4) {
                    float4 u0 = *(const float4*)(up + (kk+0)*64);
                    float4 u1 = *(const float4*)(up + (kk+1)*64);
                    float4 u2 = *(const float4*)(up + (kk+2)*64);
                    float4 u3 = *(const float4*)(up + (kk+3)*64);
                    float4 h0 = *(const float4*)(hp + kk);
                    float4 h1 = *(const float4*)(hp + HSTR   + kk);
                    float4 h2 = *(const float4*)(hp + 2*HSTR + kk);
                    float4 h3 = *(const float4*)(hp + 3*HSTR + kk);
                    FMA4(a0, h0.x, u0) FMA4(a0, h0.y, u1) FMA4(a0, h0.z, u2) FMA4(a0, h0.w, u3)
                    FMA4(a1, h1.x, u0) FMA4(a1, h1.y, u1) FMA4(a1, h1.z, u2) FMA4(a1, h1.w, u3)
                    FMA4(a2, h2.x, u0) FMA4(a2, h2.y, u1) FMA4(a2, h2.z, u2) FMA4(a2, h2.w, u3)
                    FMA4(a3, h3.x, u0) FMA4(a3, h3.y, u1) FMA4(a3, h3.z, u2) FMA4(a3, h3.w, u3)
                }
                if (kc < 3) {               // store prefetched chunk
                    float* nxt = sh_h + ((kc+1) & 1)*HBUF;
                    #pragma unroll
                    for (int j = 0; j < 8; j++) {
                        int i = tid + j*NTHR;
                        int b = i >> 5, c4 = (i & 31) << 2;
                        *(float4*)(nxt + b*HSTR + c4) = pre[j];
                    }
                }
                __syncthreads();
            }

            float4 av[4] = {a0, a1, a2, a3};
            #pragma unroll
            for (int bi = 0; bi < 4; bi++) {
                int b = (bq << 2) + bi;
                float xc[8];
                #pragma unroll
                for (int c = 0; c < 8; c++)
                    xc[c] = (c < nin) ? __ldg(xin + ((size_t)b*nin + c)*TT + t) : 0.0f;
                float sv[4] = {av[bi].x, av[bi].y, av[bi].z, av[bi].w};
                float4 r;
                float* rp = (float*)&r;
                #pragma unroll
                for (int gi = 0; gi < 4; gi++) {
                    float s = sv[gi] + biasv[gi];
                    #pragma unroll
                    for (int c = 0; c < 8; c++) s += xc[c] * wv[gi*8 + c];
                    rp[gi] = isTanh ? fast_tanh(s) : fast_sigmoid(s);
                }
                __stcg((float4*)(g_act + ((size_t)(gate*BB) + b)*HH + gbase0 + (gq << 2)), r);
            }
        }
        grid_barrier();   // g_act complete

        // ======================= Phase C: l, GEMM2, softmax, update ==========
        if (ct < 128) {
            int b  = ct >> 1;
            int gb = (ct & 1) << 8;
            // build l [512 h][8 k]: 1024 float4 tasks / 256 threads
            #pragma unroll
            for (int j = 0; j < 4; j++) {
                int i  = tid + j*NTHR;
                int k  = i >> 7;
                int h4 = (i & 127) << 2;
                int gA = (k == 0) ? 2 : (10 + k);   // candidate (tanh)
                int gB = (k == 0) ? 0 : (3 + k);    // input gate (sigmoid)
                float4 pa = __ldcg((const float4*)(g_act + ((size_t)(gA*BB) + b)*HH + h4));
                float4 pb = __ldcg((const float4*)(g_act + ((size_t)(gB*BB) + b)*HH + h4));
                sh_l[(h4+0)*8 + k] = pa.x * pb.x;
                sh_l[(h4+1)*8 + k] = pa.y * pb.y;
                sh_l[(h4+2)*8 + k] = pa.z * pb.z;
                sh_l[(h4+3)*8 + k] = pa.w * pb.w;
            }
            __syncthreads();

            int g = gb + tid;
            float acc[8] = {0,0,0,0,0,0,0,0};
            const float* wp = W_a + g;
            #pragma unroll 8
            for (int hh = 0; hh < HH; hh++) {
                float w = __ldg(wp + (size_t)hh*HH);
                float4 p0 = *(const float4*)(sh_l + hh*8);
                float4 p1 = *(const float4*)(sh_l + hh*8 + 4);
                acc[0] += p0.x*w; acc[1] += p0.y*w; acc[2] += p0.z*w; acc[3] += p0.w*w;
                acc[4] += p1.x*w; acc[5] += p1.y*w; acc[6] += p1.z*w; acc[7] += p1.w*w;
            }
            float cv = g_c[b*HH + g];
            float ba = __ldg(b_a + g);
            float u[8], m = -1e30f;
            #pragma unroll
            for (int k = 0; k < 8; k++) { u[k] = fast_tanh(acc[k]*cv + ba); m = fmaxf(m, u[k]); }
            float e[8], es = 0.0f;
            #pragma unroll
            for (int k = 0; k < 8; k++) { e[k] = __expf(u[k] - m); es += e[k]; }
            float inv = __fdividef(1.0f, es);
            float4 l0 = *(const float4*)(sh_l + g*8);
            float4 l1 = *(const float4*)(sh_l + g*8 + 4);
            float L = (e[0]*l0.x + e[1]*l0.y + e[2]*l0.z + e[3]*l0.w
                     + e[4]*l1.x + e[5]*l1.y + e[6]*l1.z + e[7]*l1.w) * inv;
            float f  = __ldcg(g_act + ((size_t)(1*BB) + b)*HH + g);
            float o  = __ldcg(g_act + ((size_t)(3*BB) + b)*HH + g);
            float cn = f*cv + L;
            float hn = o * fast_tanh(cn);
            g_c[b*HH + g] = cn;                   // private to this CTA/SM
            __stcg(g_h + b*HH + g, hn);           // consumed by all SMs next step
            out_seq[((size_t)b*TT + t)*HH + g] = hn;
            if (t == TT - 1 && out_hT) out_hT[b*HH + g] = hn;
        }
        grid_barrier();   // h/c ready for next step
    }
}

// ---------------- launch ----------------------------------------------------
extern "C" void kernel_launch(void* const* d_in, const int* in_sizes, int n_in,
                              void* d_out, int out_size) {
    (void)in_sizes; (void)n_in;
    const float* Y    = (const float*)d_in[0];
    const float* x1   = (const float*)d_in[1];
    const float* x2   = (const float*)d_in[2];
    const float* x3   = (const float*)d_in[3];
    const float* x4   = (const float*)d_in[4];
    const float* x5   = (const float*)d_in[5];
    const float* x6   = (const float*)d_in[6];
    const float* x7   = (const float*)d_in[7];
    const float* W_i  = (const float*)d_in[8];
    const float* U_i  = (const float*)d_in[9];
    const float* b_i  = (const float*)d_in[10];
    const float* W_f  = (const float*)d_in[11];
    const float* U_f  = (const float*)d_in[12];
    const float* b_f  = (const float*)d_in[13];
    const float* W_c  = (const float*)d_in[14];
    const float* U_c  = (const float*)d_in[15];
    const float* b_c  = (const float*)d_in[16];
    const float* W_o  = (const float*)d_in[17];
    const float* U_o  = (const float*)d_in[18];
    const float* b_o  = (const float*)d_in[19];
    const float* W_i_x = (const float*)d_in[20];
    const float* U_i_x = (const float*)d_in[21];
    const float* b_i_x = (const float*)d_in[22];
    const float* W_c_x = (const float*)d_in[23];
    const float* U_c_x = (const float*)d_in[24];
    const float* b_c_x = (const float*)d_in[25];
    const float* W_a  = (const float*)d_in[26];
    const float* b_a  = (const float*)d_in[27];

    float* out = (float*)d_out;
    float* out_hT; float* out_seq;
    if (out_size >= BB*HH + BB*TT*HH) { out_hT = out; out_seq = out + BB*HH; }
    else                              { out_hT = 0;   out_seq = out; }

    cudaFuncSetAttribute(lstm_kernel, cudaFuncAttributeMaxDynamicSharedMemorySize, SMEM_BYTES);

    init_kernel<<<32, NTHR>>>();
    lstm_kernel<<<NBLK, NTHR, SMEM_BYTES>>>(
        Y, x1, x2, x3, x4, x5, x6, x7,
        W_i, U_i, b_i, W_f, U_f, b_f, W_c, U_c, b_c, W_o, U_o, b_o,
        W_i_x, U_i_x, b_i_x, W_c_x, U_c_x, b_c_x, W_a, b_a,
        out_hT, out_seq);
}